// round 4
// baseline (speedup 1.0000x reference)
#include <cuda_runtime.h>
#include <cuda_bf16.h>
#include <cstdint>

// ---------------- problem constants ----------------
static constexpr int B = 512, S = 128, D = 512, A = 128;
static constexpr float EPS = 1e-7f;

// ---------------- device scratch (no allocs allowed) ----------------
__device__ __nv_bfloat16 g_wt_hi[A * D];   // W^T split-high  [a][k]
__device__ __nv_bfloat16 g_wt_lo[A * D];   // W^T split-low   [a][k]
__device__ float g_kv[B * S];
__device__ float g_mv;

// ---------------- smem layout (dynamic) ----------------
// Tiles: [128 rows][72 bf16] (64 data + 8 pad) = 18432 B each.
static constexpr int TPAD   = 72;                 // bf16 per row
static constexpr int TROWB  = TPAD * 2;           // 144 bytes per row
static constexpr int TILE_B = 128 * TROWB;        // 18432
static constexpr int OFF_XHI  = 0;
static constexpr int OFF_XLO  = OFF_XHI + TILE_B;
static constexpr int OFF_WHI  = OFF_XLO + TILE_B;
static constexpr int OFF_WLO  = OFF_WHI + TILE_B;
static constexpr int OFF_BIAS = OFF_WLO + TILE_B;       // 73728
static constexpr int OFF_U    = OFF_BIAS + 512;
static constexpr int OFF_PART = OFF_U + 512;            // float[128][2]
static constexpr int SMEM_TOTAL = OFF_PART + 1024;      // 75776

// ---------------- baseline-ISA helpers (sm_100 plain, no 'a' features) ----
__device__ __forceinline__ uint32_t smem_u32(const void* p) {
    return (uint32_t)__cvta_generic_to_shared(p);
}

#define LDSM_X4(r, addr) \
    asm volatile("ldmatrix.sync.aligned.m8n8.x4.shared.b16 {%0,%1,%2,%3}, [%4];" \
        : "=r"((r)[0]), "=r"((r)[1]), "=r"((r)[2]), "=r"((r)[3]) : "r"(addr))

#define MMA_BF16(d, a, b0, b1) \
    asm volatile("mma.sync.aligned.m16n8k16.row.col.f32.bf16.bf16.f32 " \
        "{%0,%1,%2,%3}, {%4,%5,%6,%7}, {%8,%9}, {%0,%1,%2,%3};" \
        : "+f"((d)[0]), "+f"((d)[1]), "+f"((d)[2]), "+f"((d)[3]) \
        : "r"((a)[0]), "r"((a)[1]), "r"((a)[2]), "r"((a)[3]), "r"(b0), "r"(b1))

__device__ __forceinline__ uint32_t pack_bf2(__nv_bfloat16 a, __nv_bfloat16 b) {
    return (uint32_t)__bfloat16_as_ushort(a) | ((uint32_t)__bfloat16_as_ushort(b) << 16);
}

__device__ __forceinline__ float fast_tanh(float x) {
    float a = fabsf(x);
    float t = __expf(-2.0f * a);
    float r = (1.0f - t) / (1.0f + t);
    return copysignf(r, x);
}

// ---------------- kernel 0: split + transpose W ----------------
__global__ void prep_w_kernel(const float* __restrict__ W) {
    int idx = blockIdx.x * blockDim.x + threadIdx.x;
    if (idx < D * A) {
        int k = idx / A, a = idx % A;
        float w = W[idx];
        __nv_bfloat16 hi = __float2bfloat16(w);
        float rem = w - __bfloat162float(hi);
        g_wt_hi[a * D + k] = hi;
        g_wt_lo[a * D + k] = __float2bfloat16(rem);
    }
}

// ---------------- kernel 1: fused GEMM + tanh + kv (mma.sync) ----------------
// CTA = one batch: C[128 s][128 a] = X[128, 512] @ W[512, 128], fp32 accum via
// 3-term bf16 split. 8 warps in 4x2 grid; warp tile 32(m) x 64(n).
__global__ __launch_bounds__(256, 2)
void gemm_kv_kernel(const float* __restrict__ x,
                    const float* __restrict__ bias,
                    const float* __restrict__ u) {
    extern __shared__ char smem[];
    const uint32_t sb = smem_u32(smem);
    const int tid = threadIdx.x;
    const int wid = tid >> 5;
    const int l   = tid & 31;
    const int b   = blockIdx.x;

    if (tid < A) {
        *(float*)(smem + OFF_BIAS + tid * 4) = bias[tid];
        *(float*)(smem + OFF_U + tid * 4) = u[tid];
    }

    const int wm = wid >> 1, wn = wid & 1;
    const int m0 = wm * 32, n0 = wn * 64;

    // ldmatrix lane pointer offsets (bytes, within a tile)
    const uint32_t aOff = (uint32_t)((m0 + (l & 15)) * TROWB + ((l >> 4) << 3) * 2);
    const uint32_t bOff = (uint32_t)((n0 + ((l >> 4) << 3) + (l & 7)) * TROWB
                                     + (((l >> 3) & 1) << 3) * 2);

    const float* xb = x + (size_t)b * S * D;

    float acc[2][8][4];
    #pragma unroll
    for (int mt = 0; mt < 2; mt++)
        #pragma unroll
        for (int nt = 0; nt < 8; nt++)
            #pragma unroll
            for (int q = 0; q < 4; q++) acc[mt][nt][q] = 0.0f;

    #pragma unroll 1
    for (int c = 0; c < 8; c++) {
        const int c64 = c * 64;

        // ---- load + convert X chunk (128 x 64 fp32 -> bf16 hi/lo) ----
        #pragma unroll
        for (int t = 0; t < 8; t++) {
            int slot = tid + t * 256;          // 0..2047
            int row = slot >> 4;
            int kk = (slot & 15) << 2;         // 0..60 step 4
            float4 v = *reinterpret_cast<const float4*>(xb + row * D + c64 + kk);
            __nv_bfloat16 h0 = __float2bfloat16(v.x);
            __nv_bfloat16 h1 = __float2bfloat16(v.y);
            __nv_bfloat16 h2 = __float2bfloat16(v.z);
            __nv_bfloat16 h3 = __float2bfloat16(v.w);
            __nv_bfloat16 l0 = __float2bfloat16(v.x - __bfloat162float(h0));
            __nv_bfloat16 l1 = __float2bfloat16(v.y - __bfloat162float(h1));
            __nv_bfloat16 l2 = __float2bfloat16(v.z - __bfloat162float(h2));
            __nv_bfloat16 l3 = __float2bfloat16(v.w - __bfloat162float(h3));
            uint32_t off = (uint32_t)(row * TROWB + (kk << 1));
            *reinterpret_cast<uint2*>(smem + OFF_XHI + off) =
                make_uint2(pack_bf2(h0, h1), pack_bf2(h2, h3));
            *reinterpret_cast<uint2*>(smem + OFF_XLO + off) =
                make_uint2(pack_bf2(l0, l1), pack_bf2(l2, l3));
        }
        // ---- stage W chunk (pre-split bf16, L2-resident) ----
        #pragma unroll
        for (int t = 0; t < 8; t++) {
            int slot = tid + t * 256;
            int row = slot >> 4;
            int kk = (slot & 15) << 2;
            size_t gi = (size_t)row * D + c64 + kk;
            uint32_t off = (uint32_t)(row * TROWB + (kk << 1));
            *reinterpret_cast<uint2*>(smem + OFF_WHI + off) =
                *reinterpret_cast<const uint2*>(&g_wt_hi[gi]);
            *reinterpret_cast<uint2*>(smem + OFF_WLO + off) =
                *reinterpret_cast<const uint2*>(&g_wt_lo[gi]);
        }
        __syncthreads();

        // ---- mma: 4 k-steps of 16; terms hi*hi + lo*hi + hi*lo ----
        #pragma unroll
        for (int ks = 0; ks < 4; ks++) {
            const uint32_t ko = (uint32_t)(ks * 32);   // 16 bf16 = 32 bytes
            uint32_t ah[2][4], al[2][4], bb[4][4];
            LDSM_X4(ah[0], sb + OFF_XHI + aOff + ko);
            LDSM_X4(ah[1], sb + OFF_XHI + aOff + 16 * TROWB + ko);
            LDSM_X4(al[0], sb + OFF_XLO + aOff + ko);
            LDSM_X4(al[1], sb + OFF_XLO + aOff + 16 * TROWB + ko);
            #pragma unroll
            for (int nb = 0; nb < 4; nb++)
                LDSM_X4(bb[nb], sb + OFF_WHI + bOff + nb * (16 * TROWB) + ko);
            #pragma unroll
            for (int mt = 0; mt < 2; mt++)
                #pragma unroll
                for (int nb = 0; nb < 4; nb++) {
                    MMA_BF16(acc[mt][2 * nb],     ah[mt], bb[nb][0], bb[nb][1]);
                    MMA_BF16(acc[mt][2 * nb + 1], ah[mt], bb[nb][2], bb[nb][3]);
                    MMA_BF16(acc[mt][2 * nb],     al[mt], bb[nb][0], bb[nb][1]);
                    MMA_BF16(acc[mt][2 * nb + 1], al[mt], bb[nb][2], bb[nb][3]);
                }
            #pragma unroll
            for (int nb = 0; nb < 4; nb++)
                LDSM_X4(bb[nb], sb + OFF_WLO + bOff + nb * (16 * TROWB) + ko);
            #pragma unroll
            for (int mt = 0; mt < 2; mt++)
                #pragma unroll
                for (int nb = 0; nb < 4; nb++) {
                    MMA_BF16(acc[mt][2 * nb],     ah[mt], bb[nb][0], bb[nb][1]);
                    MMA_BF16(acc[mt][2 * nb + 1], ah[mt], bb[nb][2], bb[nb][3]);
                }
        }
        __syncthreads();
    }

    // ---- epilogue: kv[m] = sum_n tanh(C[m][n] + bias[n]) * u[n] ----
    float rs[2][2] = {{0.0f, 0.0f}, {0.0f, 0.0f}};   // [m16 tile][row half]
    #pragma unroll
    for (int mt = 0; mt < 2; mt++) {
        #pragma unroll
        for (int nt = 0; nt < 8; nt++) {
            int n = n0 + nt * 8 + ((l & 3) << 1);
            float b0v = *(const float*)(smem + OFF_BIAS + n * 4);
            float b1v = *(const float*)(smem + OFF_BIAS + (n + 1) * 4);
            float u0v = *(const float*)(smem + OFF_U + n * 4);
            float u1v = *(const float*)(smem + OFF_U + (n + 1) * 4);
            rs[mt][0] += fast_tanh(acc[mt][nt][0] + b0v) * u0v
                       + fast_tanh(acc[mt][nt][1] + b1v) * u1v;
            rs[mt][1] += fast_tanh(acc[mt][nt][2] + b0v) * u0v
                       + fast_tanh(acc[mt][nt][3] + b1v) * u1v;
        }
    }
    #pragma unroll
    for (int mt = 0; mt < 2; mt++)
        #pragma unroll
        for (int h = 0; h < 2; h++) {
            float v = rs[mt][h];
            v += __shfl_xor_sync(0xFFFFFFFFu, v, 1);
            v += __shfl_xor_sync(0xFFFFFFFFu, v, 2);
            if ((l & 3) == 0) {
                int row = m0 + mt * 16 + h * 8 + (l >> 2);
                *(float*)(smem + OFF_PART + (row * 2 + wn) * 4) = v;
            }
        }
    __syncthreads();
    if (tid < S) {
        float kv = *(const float*)(smem + OFF_PART + (tid * 2) * 4)
                 + *(const float*)(smem + OFF_PART + (tid * 2 + 1) * 4);
        g_kv[b * S + tid] = kv;
    }
}

// ---------------- kernel 2: global sum of kv (double accum) ----------------
__global__ void reduce_kernel() {
    __shared__ double ssum[32];
    double acc = 0.0;
    for (int i = threadIdx.x; i < B * S; i += 1024)
        acc += (double)g_kv[i];
    #pragma unroll
    for (int o = 16; o > 0; o >>= 1)
        acc += __shfl_xor_sync(0xFFFFFFFFu, acc, o);
    if ((threadIdx.x & 31) == 0) ssum[threadIdx.x >> 5] = acc;
    __syncthreads();
    if (threadIdx.x < 32) {
        double v = ssum[threadIdx.x];
        #pragma unroll
        for (int o = 16; o > 0; o >>= 1)
            v += __shfl_xor_sync(0xFFFFFFFFu, v, o);
        if (threadIdx.x == 0) g_mv = (float)v;
    }
}

// ---------------- kernel 3: softmax + weighted pooling ----------------
__global__ __launch_bounds__(256)
void softmax_pool_kernel(const float* __restrict__ x,
                         const float* __restrict__ mask,
                         float* __restrict__ out) {
    __shared__ float sprob[S];
    __shared__ float ssum;
    const int tid = threadIdx.x;
    const int b = blockIdx.x;
    const float mv = g_mv;

    if (tid < S) {
        float e = (expf(g_kv[b * S + tid] - mv) + EPS) * mask[b * S + tid];
        sprob[tid] = e;
    }
    __syncthreads();
    if (tid < 32) {
        float v = sprob[tid] + sprob[tid + 32] + sprob[tid + 64] + sprob[tid + 96];
        #pragma unroll
        for (int o = 16; o > 0; o >>= 1)
            v += __shfl_xor_sync(0xFFFFFFFFu, v, o);
        if (tid == 0) ssum = v;
    }
    __syncthreads();
    const float inv = 1.0f / (ssum + EPS);
    if (tid < S) {
        float p = sprob[tid] * inv;
        sprob[tid] = p;
        out[B * D + b * S + tid] = p;   // prob output
    }
    __syncthreads();

    // pooled[b, d] = sum_s x[b,s,d] * prob[s]; 256 threads cover 512 d-cols
    const float* xb = x + (size_t)b * S * D;
    float acc0 = 0.0f, acc1 = 0.0f;
    #pragma unroll 4
    for (int s = 0; s < S; s++) {
        float p = sprob[s];
        acc0 += xb[(size_t)s * D + tid] * p;
        acc1 += xb[(size_t)s * D + tid + 256] * p;
    }
    out[b * D + tid] = acc0;
    out[b * D + tid + 256] = acc1;
}

// ---------------- launcher ----------------
extern "C" void kernel_launch(void* const* d_in, const int* in_sizes, int n_in,
                              void* d_out, int out_size) {
    const float* x    = (const float*)d_in[0];  // inputs  [B,S,D]
    const float* mask = (const float*)d_in[1];  // mask    [B,S,1]
    const float* W    = (const float*)d_in[2];  // kernel  [D,A]
    const float* bias = (const float*)d_in[3];  // bias    [A]
    const float* u    = (const float*)d_in[4];  // u_ctx   [A,1]
    float* out = (float*)d_out;                 // pooled [B,D] ++ prob [B,S]

    cudaFuncSetAttribute(gemm_kv_kernel,
                         cudaFuncAttributeMaxDynamicSharedMemorySize, SMEM_TOTAL);

    prep_w_kernel<<<(D * A + 255) / 256, 256>>>(W);
    gemm_kv_kernel<<<B, 256, SMEM_TOTAL>>>(x, bias, u);
    reduce_kernel<<<1, 1024>>>();
    softmax_pool_kernel<<<B, 256>>>(x, mask, out);
}

// round 5
// speedup vs baseline: 1.6207x; 1.6207x over previous
#include <cuda_runtime.h>
#include <cuda_fp16.h>
#include <cstdint>

// ---------------- problem constants ----------------
static constexpr int B = 512, S = 128, D = 512, A = 128;
static constexpr float EPS = 1e-7f;

// ---------------- device scratch (no allocs allowed) ----------------
__device__ __half g_wt[A * D];   // W^T fp16  [a][k]
__device__ float g_kv[B * S];
__device__ float g_mv;

// ---------------- smem layout (dynamic) ----------------
// Tiles: [128 rows][72 fp16] (64 data + 8 pad) = 18432 B each.
static constexpr int TPAD   = 72;
static constexpr int TROWB  = TPAD * 2;           // 144 bytes per row
static constexpr int TILE_B = 128 * TROWB;        // 18432
static constexpr int OFF_XH   = 0;
static constexpr int OFF_WH   = OFF_XH + TILE_B;
static constexpr int OFF_BIAS = OFF_WH + TILE_B;        // 36864
static constexpr int OFF_U    = OFF_BIAS + 512;
static constexpr int OFF_PART = OFF_U + 512;            // float[128][2]
static constexpr int SMEM_TOTAL = OFF_PART + 1024;      // 38912

// ---------------- baseline-ISA helpers (sm_100 plain) ----------------
__device__ __forceinline__ uint32_t smem_u32(const void* p) {
    return (uint32_t)__cvta_generic_to_shared(p);
}

#define LDSM_X4(r, addr) \
    asm volatile("ldmatrix.sync.aligned.m8n8.x4.shared.b16 {%0,%1,%2,%3}, [%4];" \
        : "=r"((r)[0]), "=r"((r)[1]), "=r"((r)[2]), "=r"((r)[3]) : "r"(addr))

#define MMA_F16(d, a, b0, b1) \
    asm volatile("mma.sync.aligned.m16n8k16.row.col.f32.f16.f16.f32 " \
        "{%0,%1,%2,%3}, {%4,%5,%6,%7}, {%8,%9}, {%0,%1,%2,%3};" \
        : "+f"((d)[0]), "+f"((d)[1]), "+f"((d)[2]), "+f"((d)[3]) \
        : "r"((a)[0]), "r"((a)[1]), "r"((a)[2]), "r"((a)[3]), "r"(b0), "r"(b1))

__device__ __forceinline__ float fast_tanh(float x) {
    float a = fabsf(x);
    float t = __expf(-2.0f * a);
    float r = (1.0f - t) / (1.0f + t);
    return copysignf(r, x);
}

// ---------------- kernel 0: transpose W to fp16 ----------------
__global__ void prep_w_kernel(const float* __restrict__ W) {
    int idx = blockIdx.x * blockDim.x + threadIdx.x;
    if (idx < D * A) {
        int k = idx / A, a = idx % A;
        g_wt[a * D + k] = __float2half_rn(W[idx]);
    }
}

// ---------------- kernel 1: fused GEMM + tanh + kv (fp16 mma.sync) --------
// CTA = one batch: C[128 s][128 a] = X[128,512] @ W[512,128], fp32 accum.
// 8 warps in 4x2 grid; warp tile 32(m) x 64(n).
__global__ __launch_bounds__(256, 2)
void gemm_kv_kernel(const float* __restrict__ x,
                    const float* __restrict__ bias,
                    const float* __restrict__ u) {
    extern __shared__ char smem[];
    const uint32_t sb = smem_u32(smem);
    const int tid = threadIdx.x;
    const int wid = tid >> 5;
    const int l   = tid & 31;
    const int b   = blockIdx.x;

    if (tid < A) {
        *(float*)(smem + OFF_BIAS + tid * 4) = bias[tid];
        *(float*)(smem + OFF_U + tid * 4) = u[tid];
    }

    const int wm = wid >> 1, wn = wid & 1;
    const int m0 = wm * 32, n0 = wn * 64;

    // ldmatrix lane pointer offsets (bytes, within a tile)
    const uint32_t aOff = (uint32_t)((m0 + (l & 15)) * TROWB + ((l >> 4) << 3) * 2);
    const uint32_t bOff = (uint32_t)((n0 + ((l >> 4) << 3) + (l & 7)) * TROWB
                                     + (((l >> 3) & 1) << 3) * 2);

    const float* xb = x + (size_t)b * S * D;

    float acc[2][8][4];
    #pragma unroll
    for (int mt = 0; mt < 2; mt++)
        #pragma unroll
        for (int nt = 0; nt < 8; nt++)
            #pragma unroll
            for (int q = 0; q < 4; q++) acc[mt][nt][q] = 0.0f;

    #pragma unroll 1
    for (int c = 0; c < 8; c++) {
        const int c64 = c * 64;

        // ---- load + convert X chunk (128 x 64 fp32 -> fp16) ----
        #pragma unroll
        for (int t = 0; t < 8; t++) {
            int slot = tid + t * 256;          // 0..2047
            int row = slot >> 4;
            int kk = (slot & 15) << 2;
            float4 v = *reinterpret_cast<const float4*>(xb + row * D + c64 + kk);
            __half2 p0 = __floats2half2_rn(v.x, v.y);
            __half2 p1 = __floats2half2_rn(v.z, v.w);
            uint32_t off = (uint32_t)(row * TROWB + (kk << 1));
            *reinterpret_cast<uint2*>(smem + OFF_XH + off) =
                make_uint2(*(uint32_t*)&p0, *(uint32_t*)&p1);
        }
        // ---- stage W chunk (pre-transposed fp16, L2-resident) ----
        #pragma unroll
        for (int t = 0; t < 8; t++) {
            int slot = tid + t * 256;
            int row = slot >> 4;
            int kk = (slot & 15) << 2;
            uint32_t off = (uint32_t)(row * TROWB + (kk << 1));
            *reinterpret_cast<uint2*>(smem + OFF_WH + off) =
                *reinterpret_cast<const uint2*>(&g_wt[(size_t)row * D + c64 + kk]);
        }
        __syncthreads();

        // ---- mma: 4 k-steps of 16 ----
        #pragma unroll
        for (int ks = 0; ks < 4; ks++) {
            const uint32_t ko = (uint32_t)(ks * 32);   // 16 fp16 = 32 bytes
            uint32_t ah[2][4], bb[4][4];
            LDSM_X4(ah[0], sb + OFF_XH + aOff + ko);
            LDSM_X4(ah[1], sb + OFF_XH + aOff + 16 * TROWB + ko);
            #pragma unroll
            for (int nb = 0; nb < 4; nb++)
                LDSM_X4(bb[nb], sb + OFF_WH + bOff + nb * (16 * TROWB) + ko);
            #pragma unroll
            for (int mt = 0; mt < 2; mt++)
                #pragma unroll
                for (int nb = 0; nb < 4; nb++) {
                    MMA_F16(acc[mt][2 * nb],     ah[mt], bb[nb][0], bb[nb][1]);
                    MMA_F16(acc[mt][2 * nb + 1], ah[mt], bb[nb][2], bb[nb][3]);
                }
        }
        __syncthreads();
    }

    // ---- epilogue: kv[m] = sum_n tanh(C[m][n] + bias[n]) * u[n] ----
    float rs[2][2] = {{0.0f, 0.0f}, {0.0f, 0.0f}};
    #pragma unroll
    for (int mt = 0; mt < 2; mt++) {
        #pragma unroll
        for (int nt = 0; nt < 8; nt++) {
            int n = n0 + nt * 8 + ((l & 3) << 1);
            float b0v = *(const float*)(smem + OFF_BIAS + n * 4);
            float b1v = *(const float*)(smem + OFF_BIAS + (n + 1) * 4);
            float u0v = *(const float*)(smem + OFF_U + n * 4);
            float u1v = *(const float*)(smem + OFF_U + (n + 1) * 4);
            rs[mt][0] += fast_tanh(acc[mt][nt][0] + b0v) * u0v
                       + fast_tanh(acc[mt][nt][1] + b1v) * u1v;
            rs[mt][1] += fast_tanh(acc[mt][nt][2] + b0v) * u0v
                       + fast_tanh(acc[mt][nt][3] + b1v) * u1v;
        }
    }
    #pragma unroll
    for (int mt = 0; mt < 2; mt++)
        #pragma unroll
        for (int h = 0; h < 2; h++) {
            float v = rs[mt][h];
            v += __shfl_xor_sync(0xFFFFFFFFu, v, 1);
            v += __shfl_xor_sync(0xFFFFFFFFu, v, 2);
            if ((l & 3) == 0) {
                int row = m0 + mt * 16 + h * 8 + (l >> 2);
                *(float*)(smem + OFF_PART + (row * 2 + wn) * 4) = v;
            }
        }
    __syncthreads();
    if (tid < S) {
        float kv = *(const float*)(smem + OFF_PART + (tid * 2) * 4)
                 + *(const float*)(smem + OFF_PART + (tid * 2 + 1) * 4);
        g_kv[b * S + tid] = kv;
    }
}

// ---------------- kernel 2: global sum of kv (double accum) ----------------
__global__ void reduce_kernel() {
    __shared__ double ssum[32];
    double acc = 0.0;
    for (int i = threadIdx.x; i < B * S; i += 1024)
        acc += (double)g_kv[i];
    #pragma unroll
    for (int o = 16; o > 0; o >>= 1)
        acc += __shfl_xor_sync(0xFFFFFFFFu, acc, o);
    if ((threadIdx.x & 31) == 0) ssum[threadIdx.x >> 5] = acc;
    __syncthreads();
    if (threadIdx.x < 32) {
        double v = ssum[threadIdx.x];
        #pragma unroll
        for (int o = 16; o > 0; o >>= 1)
            v += __shfl_xor_sync(0xFFFFFFFFu, v, o);
        if (threadIdx.x == 0) g_mv = (float)v;
    }
}

// ---------------- kernel 3: softmax + weighted pooling ----------------
// Grid {B, 2}: both halves compute the (cheap) softmax; half 0 writes prob.
// Each half pools 256 of the 512 d-columns -> 2x thread count vs before.
__global__ __launch_bounds__(256)
void softmax_pool_kernel(const float* __restrict__ x,
                         const float* __restrict__ mask,
                         float* __restrict__ out) {
    __shared__ float sprob[S];
    __shared__ float ssum;
    const int tid = threadIdx.x;
    const int b = blockIdx.x;
    const int half = blockIdx.y;
    const float mv = g_mv;

    if (tid < S) {
        float e = (expf(g_kv[b * S + tid] - mv) + EPS) * mask[b * S + tid];
        sprob[tid] = e;
    }
    __syncthreads();
    if (tid < 32) {
        float v = sprob[tid] + sprob[tid + 32] + sprob[tid + 64] + sprob[tid + 96];
        #pragma unroll
        for (int o = 16; o > 0; o >>= 1)
            v += __shfl_xor_sync(0xFFFFFFFFu, v, o);
        if (tid == 0) ssum = v;
    }
    __syncthreads();
    const float inv = 1.0f / (ssum + EPS);
    if (tid < S) {
        float p = sprob[tid] * inv;
        sprob[tid] = p;
        if (half == 0) out[B * D + b * S + tid] = p;   // prob output
    }
    __syncthreads();

    // pooled[b, d] = sum_s x[b,s,d] * prob[s]; this CTA covers 256 d-cols
    const float* xb = x + (size_t)b * S * D;
    const int d = (half << 8) + tid;
    float acc0 = 0.0f;
    #pragma unroll 8
    for (int s = 0; s < S; s++)
        acc0 += xb[(size_t)s * D + d] * sprob[s];
    out[b * D + d] = acc0;
}

// ---------------- launcher ----------------
extern "C" void kernel_launch(void* const* d_in, const int* in_sizes, int n_in,
                              void* d_out, int out_size) {
    const float* x    = (const float*)d_in[0];  // inputs  [B,S,D]
    const float* mask = (const float*)d_in[1];  // mask    [B,S,1]
    const float* W    = (const float*)d_in[2];  // kernel  [D,A]
    const float* bias = (const float*)d_in[3];  // bias    [A]
    const float* u    = (const float*)d_in[4];  // u_ctx   [A,1]
    float* out = (float*)d_out;                 // pooled [B,D] ++ prob [B,S]

    cudaFuncSetAttribute(gemm_kv_kernel,
                         cudaFuncAttributeMaxDynamicSharedMemorySize, SMEM_TOTAL);

    prep_w_kernel<<<(D * A + 255) / 256, 256>>>(W);
    gemm_kv_kernel<<<B, 256, SMEM_TOTAL>>>(x, bias, u);
    reduce_kernel<<<1, 1024>>>();
    softmax_pool_kernel<<<dim3(B, 2), 256>>>(x, mask, out);
}

// round 6
// speedup vs baseline: 1.7062x; 1.0527x over previous
#include <cuda_runtime.h>
#include <cuda_fp16.h>
#include <cstdint>

// ---------------- problem constants ----------------
static constexpr int B = 512, S = 128, D = 512, A = 128;
static constexpr float EPS = 1e-7f;

// ---------------- device scratch (no allocs allowed) ----------------
__device__ __align__(16) __half g_wt[A * D];   // W^T fp16  [a][k]
__device__ float g_kv[B * S];
__device__ float g_mv;

// ---------------- smem layout (dynamic) ----------------
// X staged as raw fp32: [2 buf][128 rows][72 f32] (64 data + 8 pad) = 36864 B/buf
// W staged as fp16:     [2 buf][128 rows][72 h]   (64 data + 8 pad) = 18432 B/buf
static constexpr int XROWB = 72 * 4;     // 288 B
static constexpr int WROWB = 72 * 2;     // 144 B
static constexpr int XBUF_B = 128 * XROWB;   // 36864
static constexpr int WBUF_B = 128 * WROWB;   // 18432
static constexpr int OFF_XF   = 0;
static constexpr int OFF_WH   = OFF_XF + 2 * XBUF_B;   // 73728
static constexpr int OFF_BIAS = OFF_WH + 2 * WBUF_B;   // 110592
static constexpr int OFF_U    = OFF_BIAS + 512;
static constexpr int OFF_PART = OFF_U + 512;           // float[128][2]
static constexpr int SMEM_TOTAL = OFF_PART + 1024;     // 112640

// ---------------- baseline-ISA helpers (sm_100 plain) ----------------
__device__ __forceinline__ uint32_t smem_u32(const void* p) {
    return (uint32_t)__cvta_generic_to_shared(p);
}

#define CP_ASYNC16(dst, src) \
    asm volatile("cp.async.cg.shared.global [%0], [%1], 16;" :: "r"(dst), "l"(src))
#define CP_COMMIT() asm volatile("cp.async.commit_group;")
#define CP_WAIT_ALL() asm volatile("cp.async.wait_group 0;")

#define LDSM_X4(r, addr) \
    asm volatile("ldmatrix.sync.aligned.m8n8.x4.shared.b16 {%0,%1,%2,%3}, [%4];" \
        : "=r"((r)[0]), "=r"((r)[1]), "=r"((r)[2]), "=r"((r)[3]) : "r"(addr))

#define MMA_F16(d, a, b0, b1) \
    asm volatile("mma.sync.aligned.m16n8k16.row.col.f32.f16.f16.f32 " \
        "{%0,%1,%2,%3}, {%4,%5,%6,%7}, {%8,%9}, {%0,%1,%2,%3};" \
        : "+f"((d)[0]), "+f"((d)[1]), "+f"((d)[2]), "+f"((d)[3]) \
        : "r"((a)[0]), "r"((a)[1]), "r"((a)[2]), "r"((a)[3]), "r"(b0), "r"(b1))

__device__ __forceinline__ uint32_t f2h2(float a, float b) {
    __half2 h = __floats2half2_rn(a, b);
    return *(uint32_t*)&h;
}

__device__ __forceinline__ float fast_tanh(float x) {
    float a = fabsf(x);
    float t = __expf(-2.0f * a);
    float r = (1.0f - t) / (1.0f + t);
    return copysignf(r, x);
}

// ---------------- kernel 0: transpose W to fp16 ----------------
__global__ void prep_w_kernel(const float* __restrict__ W) {
    int idx = blockIdx.x * blockDim.x + threadIdx.x;
    if (idx < D * A) {
        int k = idx / A, a = idx % A;
        g_wt[a * D + k] = __float2half_rn(W[idx]);
    }
}

// ---------------- kernel 1: fused GEMM + tanh + kv ----------------
// CTA = one batch. cp.async double-buffered pipeline; A-frags built from
// fp32 smem via LDS.64+cvt, B-frags via ldmatrix on fp16 smem.
__global__ __launch_bounds__(256, 2)
void gemm_kv_kernel(const float* __restrict__ x,
                    const float* __restrict__ bias,
                    const float* __restrict__ u) {
    extern __shared__ char smem[];
    const uint32_t sb = smem_u32(smem);
    const int tid = threadIdx.x;
    const int wid = tid >> 5;
    const int l   = tid & 31;
    const int b   = blockIdx.x;

    if (tid < A) {
        *(float*)(smem + OFF_BIAS + tid * 4) = bias[tid];
        *(float*)(smem + OFF_U + tid * 4) = u[tid];
    }

    const int wm = wid >> 1, wn = wid & 1;
    const int m0 = wm * 32, n0 = wn * 64;

    const float* xb = x + (size_t)b * S * D;

    // cp.async slot decomposition (per chunk):
    //  X: 2048 x 16B ops -> 8/thread: row = slot>>4, j = slot&15
    //  W: 1024 x 16B ops -> 4/thread: row = slot>>3, j = slot&7
    const int xrow = tid >> 1;              // pairs: tid covers 128 rows x 2 j-groups
    // (use generic slot math below instead)

    // A-fragment lane geometry
    const int ar = l >> 2;                  // 0..7
    const int ac = (l & 3) << 1;            // 0,2,4,6
    // B-fragment ldmatrix pointer (within a W buffer)
    const uint32_t bOff = (uint32_t)((n0 + ((l >> 4) << 3) + (l & 7)) * WROWB
                                     + (((l >> 3) & 1) << 3) * 2);

    float acc[2][8][4];
    #pragma unroll
    for (int mt = 0; mt < 2; mt++)
        #pragma unroll
        for (int nt = 0; nt < 8; nt++)
            #pragma unroll
            for (int q = 0; q < 4; q++) acc[mt][nt][q] = 0.0f;

    // ---- issue chunk 0 ----
    {
        const int c64 = 0;
        #pragma unroll
        for (int t = 0; t < 8; t++) {
            int slot = tid + t * 256;
            int row = slot >> 4, j = slot & 15;
            CP_ASYNC16(sb + OFF_XF + row * XROWB + j * 16,
                       (const char*)(xb + (size_t)row * D + c64) + j * 16);
        }
        #pragma unroll
        for (int t = 0; t < 4; t++) {
            int slot = tid + t * 256;
            int row = slot >> 3, j = slot & 7;
            CP_ASYNC16(sb + OFF_WH + row * WROWB + j * 16,
                       (const char*)(g_wt + (size_t)row * D + c64) + j * 16);
        }
        CP_COMMIT();
    }

    #pragma unroll 1
    for (int c = 0; c < 8; c++) {
        CP_WAIT_ALL();
        __syncthreads();

        if (c < 7) {
            const int c64 = (c + 1) * 64;
            const uint32_t xB = sb + OFF_XF + ((c + 1) & 1) * XBUF_B;
            const uint32_t wB = sb + OFF_WH + ((c + 1) & 1) * WBUF_B;
            #pragma unroll
            for (int t = 0; t < 8; t++) {
                int slot = tid + t * 256;
                int row = slot >> 4, j = slot & 15;
                CP_ASYNC16(xB + row * XROWB + j * 16,
                           (const char*)(xb + (size_t)row * D + c64) + j * 16);
            }
            #pragma unroll
            for (int t = 0; t < 4; t++) {
                int slot = tid + t * 256;
                int row = slot >> 3, j = slot & 7;
                CP_ASYNC16(wB + row * WROWB + j * 16,
                           (const char*)(g_wt + (size_t)row * D + c64) + j * 16);
            }
            CP_COMMIT();
        }

        const uint32_t xF = sb + OFF_XF + (c & 1) * XBUF_B;
        const uint32_t wH = sb + OFF_WH + (c & 1) * WBUF_B;

        #pragma unroll
        for (int ks = 0; ks < 4; ks++) {
            const int kc = ks * 16;
            uint32_t ah[2][4], bb[4][4];
            #pragma unroll
            for (int mt = 0; mt < 2; mt++) {
                const uint32_t base = xF + (m0 + mt * 16 + ar) * XROWB + (kc + ac) * 4;
                float2 v0 = *(const float2*)(smem + (base - sb));
                float2 v1 = *(const float2*)(smem + (base - sb) + 8 * XROWB);
                float2 v2 = *(const float2*)(smem + (base - sb) + 32);
                float2 v3 = *(const float2*)(smem + (base - sb) + 8 * XROWB + 32);
                ah[mt][0] = f2h2(v0.x, v0.y);
                ah[mt][1] = f2h2(v1.x, v1.y);
                ah[mt][2] = f2h2(v2.x, v2.y);
                ah[mt][3] = f2h2(v3.x, v3.y);
            }
            #pragma unroll
            for (int nb = 0; nb < 4; nb++)
                LDSM_X4(bb[nb], wH + bOff + nb * (16 * WROWB) + kc * 2);
            #pragma unroll
            for (int mt = 0; mt < 2; mt++)
                #pragma unroll
                for (int nb = 0; nb < 4; nb++) {
                    MMA_F16(acc[mt][2 * nb],     ah[mt], bb[nb][0], bb[nb][1]);
                    MMA_F16(acc[mt][2 * nb + 1], ah[mt], bb[nb][2], bb[nb][3]);
                }
        }
        __syncthreads();
    }

    // ---- epilogue: kv[m] = sum_n tanh(C[m][n] + bias[n]) * u[n] ----
    float rs[2][2] = {{0.0f, 0.0f}, {0.0f, 0.0f}};
    #pragma unroll
    for (int mt = 0; mt < 2; mt++) {
        #pragma unroll
        for (int nt = 0; nt < 8; nt++) {
            int n = n0 + nt * 8 + ((l & 3) << 1);
            float b0v = *(const float*)(smem + OFF_BIAS + n * 4);
            float b1v = *(const float*)(smem + OFF_BIAS + (n + 1) * 4);
            float u0v = *(const float*)(smem + OFF_U + n * 4);
            float u1v = *(const float*)(smem + OFF_U + (n + 1) * 4);
            rs[mt][0] += fast_tanh(acc[mt][nt][0] + b0v) * u0v
                       + fast_tanh(acc[mt][nt][1] + b1v) * u1v;
            rs[mt][1] += fast_tanh(acc[mt][nt][2] + b0v) * u0v
                       + fast_tanh(acc[mt][nt][3] + b1v) * u1v;
        }
    }
    #pragma unroll
    for (int mt = 0; mt < 2; mt++)
        #pragma unroll
        for (int h = 0; h < 2; h++) {
            float v = rs[mt][h];
            v += __shfl_xor_sync(0xFFFFFFFFu, v, 1);
            v += __shfl_xor_sync(0xFFFFFFFFu, v, 2);
            if ((l & 3) == 0) {
                int row = m0 + mt * 16 + h * 8 + (l >> 2);
                *(float*)(smem + OFF_PART + (row * 2 + wn) * 4) = v;
            }
        }
    __syncthreads();
    if (tid < S) {
        float kv = *(const float*)(smem + OFF_PART + (tid * 2) * 4)
                 + *(const float*)(smem + OFF_PART + (tid * 2 + 1) * 4);
        g_kv[b * S + tid] = kv;
    }
}

// ---------------- kernel 2: global sum of kv (double accum) ----------------
__global__ void reduce_kernel() {
    __shared__ double ssum[32];
    double acc = 0.0;
    for (int i = threadIdx.x; i < B * S; i += 1024)
        acc += (double)g_kv[i];
    #pragma unroll
    for (int o = 16; o > 0; o >>= 1)
        acc += __shfl_xor_sync(0xFFFFFFFFu, acc, o);
    if ((threadIdx.x & 31) == 0) ssum[threadIdx.x >> 5] = acc;
    __syncthreads();
    if (threadIdx.x < 32) {
        double v = ssum[threadIdx.x];
        #pragma unroll
        for (int o = 16; o > 0; o >>= 1)
            v += __shfl_xor_sync(0xFFFFFFFFu, v, o);
        if (threadIdx.x == 0) g_mv = (float)v;
    }
}

// ---------------- kernel 3: softmax + weighted pooling (float4) ----------
// Grid {B, 2}: each y-half covers 256 d-cols (64 float4), s split 4-way.
__global__ __launch_bounds__(256)
void softmax_pool_kernel(const float* __restrict__ x,
                         const float* __restrict__ mask,
                         float* __restrict__ out) {
    __shared__ float sprob[S];
    __shared__ float ssum;
    __shared__ float4 spart[4][64];
    const int tid = threadIdx.x;
    const int b = blockIdx.x;
    const int half = blockIdx.y;
    const float mv = g_mv;

    if (tid < S) {
        float e = (expf(g_kv[b * S + tid] - mv) + EPS) * mask[b * S + tid];
        sprob[tid] = e;
    }
    __syncthreads();
    if (tid < 32) {
        float v = sprob[tid] + sprob[tid + 32] + sprob[tid + 64] + sprob[tid + 96];
        #pragma unroll
        for (int o = 16; o > 0; o >>= 1)
            v += __shfl_xor_sync(0xFFFFFFFFu, v, o);
        if (tid == 0) ssum = v;
    }
    __syncthreads();
    const float inv = 1.0f / (ssum + EPS);
    if (tid < S) {
        float p = sprob[tid] * inv;
        sprob[tid] = p;
        if (half == 0) out[B * D + b * S + tid] = p;   // prob output
    }
    __syncthreads();

    // pooling: thread = (sq, dq); dq in [0,64) float4 cols, sq in [0,4) s-quarters
    const int dq = tid & 63;
    const int sq = tid >> 6;
    const float* xb = x + (size_t)b * S * D + half * 256;
    float4 acc = make_float4(0.f, 0.f, 0.f, 0.f);
    #pragma unroll 8
    for (int s = sq * 32; s < sq * 32 + 32; s++) {
        float4 v = *(const float4*)(xb + (size_t)s * D + dq * 4);
        float p = sprob[s];
        acc.x += v.x * p; acc.y += v.y * p; acc.z += v.z * p; acc.w += v.w * p;
    }
    spart[sq][dq] = acc;
    __syncthreads();
    if (tid < 64) {
        float4 a0 = spart[0][tid], a1 = spart[1][tid];
        float4 a2 = spart[2][tid], a3 = spart[3][tid];
        float4 r = make_float4(a0.x + a1.x + a2.x + a3.x,
                               a0.y + a1.y + a2.y + a3.y,
                               a0.z + a1.z + a2.z + a3.z,
                               a0.w + a1.w + a2.w + a3.w);
        *(float4*)(out + b * D + half * 256 + tid * 4) = r;
    }
}

// ---------------- launcher ----------------
extern "C" void kernel_launch(void* const* d_in, const int* in_sizes, int n_in,
                              void* d_out, int out_size) {
    const float* x    = (const float*)d_in[0];  // inputs  [B,S,D]
    const float* mask = (const float*)d_in[1];  // mask    [B,S,1]
    const float* W    = (const float*)d_in[2];  // kernel  [D,A]
    const float* bias = (const float*)d_in[3];  // bias    [A]
    const float* u    = (const float*)d_in[4];  // u_ctx   [A,1]
    float* out = (float*)d_out;                 // pooled [B,D] ++ prob [B,S]

    cudaFuncSetAttribute(gemm_kv_kernel,
                         cudaFuncAttributeMaxDynamicSharedMemorySize, SMEM_TOTAL);

    prep_w_kernel<<<(D * A + 255) / 256, 256>>>(W);
    gemm_kv_kernel<<<B, 256, SMEM_TOTAL>>>(x, bias, u);
    reduce_kernel<<<1, 1024>>>();
    softmax_pool_kernel<<<dim3(B, 2), 256>>>(x, mask, out);
}